// round 14
// baseline (speedup 1.0000x reference)
#include <cuda_runtime.h>
#include <cuda_bf16.h>
#include <cstdint>

// SC2_KNN: deformed = pc1 + pred_flow; voxelize into (800,800,45) grid
// (cell 0.1 => multiply by 10.0f, matching XLA's A/const -> A*(1/const)
// rewrite where fp32(1/0.1f) == 10.0f exactly); gather nn_cell from
// full_ids (3 channels), gather nn_idx from orig_index_grid, distance to
// pc2[nn_idx]. Outputs: dist[N] then idx[N] (as float) concatenated.
//
// R14: fill-granularity probe. Cold profile shows ~128B of DRAM fill per
// random 4B gather (sector promotion). full_ids (77 MB line footprint,
// can't stay L2-resident, dominant miss source) switches to __ldcv
// (no-cache fetch): if .cv skips 128B promotion, each miss costs ~one
// 32B sector (4x less DRAM), and the ~77 MB of freed L2 capacity
// guarantees grid+pc2 (~28 MB) full cross-replay residency on default
// .ca. Streams stay .cs evict-first; 128-thread blocks; 1 pt/thread.

#define GXD 800
#define GYD 800
#define GZD 45

__global__ __launch_bounds__(128) void SC2_KNN_kernel(
                               const float* __restrict__ pc1,
                               const float* __restrict__ flow,
                               const float* __restrict__ pc2,
                               const int*   __restrict__ full_ids,
                               const int*   __restrict__ grid,
                               float*       __restrict__ out,
                               int n) {
    int i = blockIdx.x * blockDim.x + threadIdx.x;
    if (i >= n) return;

    // coalesced streaming point loads (evict-first: no cache churn)
    float d0 = __fadd_rn(__ldcs(pc1 + 3 * i + 0), __ldcs(flow + 3 * i + 0));
    float d1 = __fadd_rn(__ldcs(pc1 + 3 * i + 1), __ldcs(flow + 3 * i + 1));
    float d2 = __fadd_rn(__ldcs(pc1 + 3 * i + 2), __ldcs(flow + 3 * i + 2));

    // voxelize: (d - min_range) * 10.0f, truncate, clip.
    int gx = (int)__fmul_rn(__fadd_rn(d0, 40.0f), 10.0f);
    int gy = (int)__fmul_rn(__fadd_rn(d1, 40.0f), 10.0f);
    int gz = (int)__fmul_rn(__fadd_rn(d2,  1.0f), 10.0f);
    gx = min(max(gx, 0), GXD - 1);
    gy = min(max(gy, 0), GYD - 1);
    gz = min(max(gz, 0), GZD - 1);

    // full_ids: shape (3, GX, GY, GZ), channel stride 28,800,000 (< 2^31).
    // __ldcv: no-cache fetch -> no L2 allocation (frees capacity for
    // grid+pc2), and tests sector-vs-line DRAM fill granularity.
    const int CH = GXD * GYD * GZD;
    int cell = (gx * GYD + gy) * GZD + gz;
    int c0 = __ldcv(full_ids + cell);
    int c1 = __ldcv(full_ids + CH + cell);
    int c2 = __ldcv(full_ids + 2 * CH + cell);

    // orig_index_grid (26 MB line footprint) + pc2 (2.4 MB): default .ca,
    // now guaranteed L2-resident across replays with full_ids out of L2.
    int nn = grid[(c0 * GYD + c1) * GZD + c2];

    float x = pc2[3 * nn + 0] - d0;
    float y = pc2[3 * nn + 1] - d1;
    float z = pc2[3 * nn + 2] - d2;
    float dist = sqrtf(x * x + y * y + z * z);

    __stcs(out + i,     dist);
    __stcs(out + n + i, (float)nn);
}

extern "C" void kernel_launch(void* const* d_in, const int* in_sizes, int n_in,
                              void* d_out, int out_size) {
    const float* pc1      = (const float*)d_in[0];
    const float* flow     = (const float*)d_in[1];
    const float* pc2      = (const float*)d_in[2];
    const int*   full_ids = (const int*)d_in[3];
    const int*   grid     = (const int*)d_in[4];
    float*       out      = (float*)d_out;

    int n = in_sizes[0] / 3;           // pc1 has (1, N, 3) -> 3N elements
    int threads = 128;
    int blocks  = (n + threads - 1) / threads;
    SC2_KNN_kernel<<<blocks, threads>>>(pc1, flow, pc2, full_ids, grid, out, n);
}

// round 15
// speedup vs baseline: 1.1544x; 1.1544x over previous
#include <cuda_runtime.h>
#include <cuda_bf16.h>
#include <cstdint>

// SC2_KNN final (R15): deformed = pc1 + pred_flow; voxelize into the
// (800,800,45) grid (cell 0.1 => multiply by 10.0f, matching XLA's
// A/const -> A*(1/const) rewrite where fp32(1/0.1f) == 10.0f exactly);
// gather nn_cell from full_ids (3 channels), nn_idx from
// orig_index_grid, distance to pc2[nn_idx]. Outputs: dist[N] then
// idx[N] (as float) concatenated.
//
// Converged config after 14 measured rounds (best 12.77 us):
//  - 1 point/thread, 256-thread blocks (2pt/thread regresses warm: R12;
//    block size 128 vs 256 is noise: R10)
//  - scalar 4B gathers: wavefront-minimal for random access (v2
//    regresses: R11)
//  - index gathers via __ldcg (L2-only; zero L1 reuse on a ~100 MB set,
//    keeps L2 partial cross-replay residency that .cv discards: R14)
//  - pc2 via default .ca (only array with L1 reuse)
//  - pc1/flow/out via .cs evict-first (protects the L2-held gather set;
//    retaining streams instead regresses: R9)
// Remaining time = L1tex random-wavefront floor (7 wf/point) overlapped
// with residual DRAM misses of a line set that oversubscribes L2.

#define GXD 800
#define GYD 800
#define GZD 45

__global__ __launch_bounds__(256) void SC2_KNN_kernel(
                               const float* __restrict__ pc1,
                               const float* __restrict__ flow,
                               const float* __restrict__ pc2,
                               const int*   __restrict__ full_ids,
                               const int*   __restrict__ grid,
                               float*       __restrict__ out,
                               int n) {
    int i = blockIdx.x * blockDim.x + threadIdx.x;
    if (i >= n) return;

    // coalesced streaming point loads (evict-first: no cache churn)
    float d0 = __fadd_rn(__ldcs(pc1 + 3 * i + 0), __ldcs(flow + 3 * i + 0));
    float d1 = __fadd_rn(__ldcs(pc1 + 3 * i + 1), __ldcs(flow + 3 * i + 1));
    float d2 = __fadd_rn(__ldcs(pc1 + 3 * i + 2), __ldcs(flow + 3 * i + 2));

    // voxelize: (d - min_range) * 10.0f, truncate, clip.
    int gx = (int)__fmul_rn(__fadd_rn(d0, 40.0f), 10.0f);
    int gy = (int)__fmul_rn(__fadd_rn(d1, 40.0f), 10.0f);
    int gz = (int)__fmul_rn(__fadd_rn(d2,  1.0f), 10.0f);
    gx = min(max(gx, 0), GXD - 1);
    gy = min(max(gy, 0), GYD - 1);
    gz = min(max(gz, 0), GZD - 1);

    // full_ids: shape (3, GX, GY, GZ), channel stride 28,800,000 (< 2^31).
    // L2-only gathers: no L1 allocation, keep L2 partial residency.
    const int CH = GXD * GYD * GZD;
    int cell = (gx * GYD + gy) * GZD + gz;
    int c0 = __ldcg(full_ids + cell);
    int c1 = __ldcg(full_ids + CH + cell);
    int c2 = __ldcg(full_ids + 2 * CH + cell);

    // orig_index_grid: shape (GX, GY, GZ) — L2-only as well.
    int nn = __ldcg(grid + (c0 * GYD + c1) * GZD + c2);

    // pc2[3*nn..3*nn+2]: default .ca — the only L1-resident array.
    float x = pc2[3 * nn + 0] - d0;
    float y = pc2[3 * nn + 1] - d1;
    float z = pc2[3 * nn + 2] - d2;
    float dist = sqrtf(x * x + y * y + z * z);

    __stcs(out + i,     dist);
    __stcs(out + n + i, (float)nn);
}

extern "C" void kernel_launch(void* const* d_in, const int* in_sizes, int n_in,
                              void* d_out, int out_size) {
    const float* pc1      = (const float*)d_in[0];
    const float* flow     = (const float*)d_in[1];
    const float* pc2      = (const float*)d_in[2];
    const int*   full_ids = (const int*)d_in[3];
    const int*   grid     = (const int*)d_in[4];
    float*       out      = (float*)d_out;

    int n = in_sizes[0] / 3;           // pc1 has (1, N, 3) -> 3N elements
    int threads = 256;
    int blocks  = (n + threads - 1) / threads;
    SC2_KNN_kernel<<<blocks, threads>>>(pc1, flow, pc2, full_ids, grid, out, n);
}

// round 16
// speedup vs baseline: 1.1805x; 1.0226x over previous
#include <cuda_runtime.h>
#include <cuda_bf16.h>
#include <cstdint>

// SC2_KNN final (R16): deformed = pc1 + pred_flow; voxelize into the
// (800,800,45) grid (cell 0.1 => multiply by 10.0f, matching XLA's
// A/const -> A*(1/const) rewrite where fp32(1/0.1f) == 10.0f exactly);
// gather nn_cell from full_ids (3 channels), nn_idx from
// orig_index_grid, distance to pc2[nn_idx]. Outputs: dist[N] then
// idx[N] (as float) concatenated.
//
// Last untested cell of the (L1 policy x L2 hint) matrix: index gathers
// use .cg L1-bypass (pc2 stays the only L1 tenant, R13) COMBINED with
// the createpolicy evict_last L2 hint (best L2 behavior, R7). Everything
// else is the converged config: 1 pt/thread, 256-thread blocks, scalar
// 4B gathers (wavefront-minimal), pc2 default .ca, pc1/flow/out .cs
// evict-first. Measured map: R7 12.77 / R10 12.80 / R13 12.80 /
// R15 13.06; regressions: v2 gathers, 2pt/thread, .cv, stream retention.

#define GXD 800
#define GYD 800
#define GZD 45

__device__ __forceinline__ uint64_t evict_last_policy() {
    uint64_t pol;
    asm("createpolicy.fractional.L2::evict_last.b64 %0, 1.0;" : "=l"(pol));
    return pol;
}
// L1-bypass (.cg) gather with evict_last L2 hint
__device__ __forceinline__ int ldcg_hint_i32(const int* p, uint64_t pol) {
    int v;
    asm("ld.global.cg.L2::cache_hint.s32 %0, [%1], %2;"
        : "=r"(v) : "l"(p), "l"(pol));
    return v;
}
__device__ __forceinline__ float ldca_hint_f32(const float* p, uint64_t pol) {
    float v;
    asm("ld.global.ca.L2::cache_hint.f32 %0, [%1], %2;"
        : "=f"(v) : "l"(p), "l"(pol));
    return v;
}

__global__ __launch_bounds__(256) void SC2_KNN_kernel(
                               const float* __restrict__ pc1,
                               const float* __restrict__ flow,
                               const float* __restrict__ pc2,
                               const int*   __restrict__ full_ids,
                               const int*   __restrict__ grid,
                               float*       __restrict__ out,
                               int n) {
    int i = blockIdx.x * blockDim.x + threadIdx.x;
    if (i >= n) return;

    uint64_t pol = evict_last_policy();

    // coalesced streaming point loads (evict-first: no cache churn)
    float d0 = __fadd_rn(__ldcs(pc1 + 3 * i + 0), __ldcs(flow + 3 * i + 0));
    float d1 = __fadd_rn(__ldcs(pc1 + 3 * i + 1), __ldcs(flow + 3 * i + 1));
    float d2 = __fadd_rn(__ldcs(pc1 + 3 * i + 2), __ldcs(flow + 3 * i + 2));

    // voxelize: (d - min_range) * 10.0f, truncate, clip.
    int gx = (int)__fmul_rn(__fadd_rn(d0, 40.0f), 10.0f);
    int gy = (int)__fmul_rn(__fadd_rn(d1, 40.0f), 10.0f);
    int gz = (int)__fmul_rn(__fadd_rn(d2,  1.0f), 10.0f);
    gx = min(max(gx, 0), GXD - 1);
    gy = min(max(gy, 0), GYD - 1);
    gz = min(max(gz, 0), GZD - 1);

    // full_ids: shape (3, GX, GY, GZ), channel stride 28,800,000 (< 2^31).
    // .cg + evict_last: no L1 allocation, retained in L2 across replays.
    const int CH = GXD * GYD * GZD;
    int cell = (gx * GYD + gy) * GZD + gz;
    int c0 = ldcg_hint_i32(full_ids + cell,          pol);
    int c1 = ldcg_hint_i32(full_ids + CH + cell,     pol);
    int c2 = ldcg_hint_i32(full_ids + 2 * CH + cell, pol);

    // orig_index_grid: shape (GX, GY, GZ) — same policy.
    int nn = ldcg_hint_i32(grid + (c0 * GYD + c1) * GZD + c2, pol);

    // pc2[3*nn..3*nn+2]: .ca + evict_last — the only L1-resident array.
    float x = ldca_hint_f32(pc2 + 3 * nn + 0, pol) - d0;
    float y = ldca_hint_f32(pc2 + 3 * nn + 1, pol) - d1;
    float z = ldca_hint_f32(pc2 + 3 * nn + 2, pol) - d2;
    float dist = sqrtf(x * x + y * y + z * z);

    __stcs(out + i,     dist);
    __stcs(out + n + i, (float)nn);
}

extern "C" void kernel_launch(void* const* d_in, const int* in_sizes, int n_in,
                              void* d_out, int out_size) {
    const float* pc1      = (const float*)d_in[0];
    const float* flow     = (const float*)d_in[1];
    const float* pc2      = (const float*)d_in[2];
    const int*   full_ids = (const int*)d_in[3];
    const int*   grid     = (const int*)d_in[4];
    float*       out      = (float*)d_out;

    int n = in_sizes[0] / 3;           // pc1 has (1, N, 3) -> 3N elements
    int threads = 256;
    int blocks  = (n + threads - 1) / threads;
    SC2_KNN_kernel<<<blocks, threads>>>(pc1, flow, pc2, full_ids, grid, out, n);
}